// round 11
// baseline (speedup 1.0000x reference)
#include <cuda_runtime.h>
#include <cuda_bf16.h>
#include <math.h>
#include <stdint.h>

#define HIDDEN 2048
#define INTER  768
#define NE     32
#define TOPK   8
#define MAXT   512
#define MAXP   (MAXT * TOPK)

typedef unsigned short ushort_t;

// ---- scratch (device globals) ----
__device__ float g_topw[MAXP];
__device__ int   g_topi[MAXP];
__device__ int   g_cnt[NE];
__device__ int   g_off[NE];
__device__ int   g_pt[MAXP];
__device__ int   g_t2p[MAXP];
__device__ ushort_t g_x_hi[(size_t)MAXT * HIDDEN];
__device__ ushort_t g_x_lo[(size_t)MAXT * HIDDEN];
__device__ ushort_t g_act_hi[(size_t)MAXP * INTER];
__device__ ushort_t g_act_lo[(size_t)MAXP * INTER];
__device__ float g_eout[(size_t)MAXP * HIDDEN];

// ================= helpers =================
__device__ __forceinline__ uint32_t smem_u32(const void* p) {
    uint32_t a;
    asm("{ .reg .u64 t; cvta.to.shared.u64 t, %1; cvt.u32.u64 %0, t; }" : "=r"(a) : "l"(p));
    return a;
}
__device__ __forceinline__ void cpa16z(uint32_t dst, const void* src, int zf) {
    asm volatile("cp.async.ca.shared.global [%0], [%1], 16, %2;" :: "r"(dst), "l"(src), "r"(zf));
}
#define CP_COMMIT() asm volatile("cp.async.commit_group;" ::: "memory")
#define CP_WAIT0()  asm volatile("cp.async.wait_group 0;" ::: "memory")
#define CP_WAIT1()  asm volatile("cp.async.wait_group 1;" ::: "memory")

__device__ __forceinline__ void ldsm4(uint32_t* r, uint32_t addr) {
    asm volatile("ldmatrix.sync.aligned.m8n8.x4.shared.b16 {%0,%1,%2,%3}, [%4];"
        : "=r"(r[0]), "=r"(r[1]), "=r"(r[2]), "=r"(r[3]) : "r"(addr));
}

__device__ __forceinline__ unsigned short bfh(float v) { return __bfloat16_as_ushort(__float2bfloat16(v)); }

// cheap split: hi = truncated top-16 bits (exact residual), lo = RN-bf16 of residual
__device__ __forceinline__ void split2t(float a, float b, uint32_t& hi, uint32_t& lo) {
    uint32_t ua = __float_as_uint(a), ub = __float_as_uint(b);
    hi = __byte_perm(ua, ub, 0x7632);
    float ra = a - __uint_as_float(ua & 0xFFFF0000u);
    float rb = b - __uint_as_float(ub & 0xFFFF0000u);
    asm("cvt.rn.bf16x2.f32 %0, %1, %2;" : "=r"(lo) : "f"(rb), "f"(ra));
}

__device__ __forceinline__ void mma16816(float* c, const uint32_t* a, const uint32_t* b) {
    asm volatile(
        "mma.sync.aligned.m16n8k16.row.col.f32.bf16.bf16.f32 "
        "{%0,%1,%2,%3}, {%4,%5,%6,%7}, {%8,%9}, {%0,%1,%2,%3};"
        : "+f"(c[0]), "+f"(c[1]), "+f"(c[2]), "+f"(c[3])
        : "r"(a[0]), "r"(a[1]), "r"(a[2]), "r"(a[3]), "r"(b[0]), "r"(b[1]));
}

#define AS 40        // A smem row stride (ushorts); 80B rows
#define GB_ROW 1056  // e1 B row stride bytes
#define GB_HALF 512
#define GB_ROW2 2080 // e2 B row stride bytes
#define GB_HALF2 1024

// ================= small kernels =================
__global__ void prep_x_kernel(const float* __restrict__ x, int nTot) {
    int i = (blockIdx.x * 256 + threadIdx.x) * 4;
    if (i < nTot) {
        float4 v = *(const float4*)(x + i);
        uint2 H, L;
        split2t(v.x, v.y, H.x, L.x);
        split2t(v.z, v.w, H.y, L.y);
        *(uint2*)&g_x_hi[i] = H;
        *(uint2*)&g_x_lo[i] = L;
    }
}

__global__ void router_kernel(const float* __restrict__ x, const float* __restrict__ gw) {
    int t = blockIdx.x;
    __shared__ float xs[HIDDEN];
    __shared__ float logits[NE];
    int tid = threadIdx.x;
    for (int i = tid; i < HIDDEN; i += 128) xs[i] = x[(size_t)t * HIDDEN + i];
    __syncthreads();
    int warp = tid >> 5, lane = tid & 31;
    for (int e8 = 0; e8 < 8; e8++) {
        int e = warp * 8 + e8;
        const float* w = gw + (size_t)e * HIDDEN;
        float s = 0.f;
        for (int h = lane; h < HIDDEN; h += 32) s += xs[h] * w[h];
        #pragma unroll
        for (int o = 16; o; o >>= 1) s += __shfl_xor_sync(0xffffffffu, s, o);
        if (lane == 0) logits[e] = s;
    }
    __syncthreads();
    if (tid == 0) {
        float mx = -1e30f;
        for (int e = 0; e < NE; e++) mx = fmaxf(mx, logits[e]);
        float p[NE];
        for (int e = 0; e < NE; e++) p[e] = expf(logits[e] - mx);
        bool used[NE] = {};
        float wsum = 0.f; int idx[TOPK]; float wv[TOPK];
        for (int k = 0; k < TOPK; k++) {
            float best = -1.f; int bi = 0;
            for (int e = 0; e < NE; e++)
                if (!used[e] && p[e] > best) { best = p[e]; bi = e; }
            used[bi] = true; idx[k] = bi; wv[k] = best; wsum += best;
        }
        float inv = 1.f / wsum;
        for (int k = 0; k < TOPK; k++) {
            g_topi[t * TOPK + k] = idx[k];
            g_topw[t * TOPK + k] = wv[k] * inv;
        }
    }
}

__global__ void build_kernel(int T) {
    __shared__ int cnt[NE], cur[NE];
    int tid = threadIdx.x;
    int np = T * TOPK;
    if (tid < NE) cnt[tid] = 0;
    __syncthreads();
    for (int p = tid; p < np; p += blockDim.x) atomicAdd(&cnt[g_topi[p]], 1);
    __syncthreads();
    if (tid == 0) {
        int off = 0;
        for (int e = 0; e < NE; e++) {
            g_off[e] = off; g_cnt[e] = cnt[e]; cur[e] = off; off += cnt[e];
        }
    }
    __syncthreads();
    for (int p = tid; p < np; p += blockDim.x) {
        int e = g_topi[p];
        int j = atomicAdd(&cur[e], 1);
        g_pt[j] = p >> 3;
        g_t2p[p] = j;
    }
}

__global__ void combine_kernel(float* __restrict__ y) {
    int t = blockIdx.x, tid = threadIdx.x;
    __shared__ int   pj[TOPK];
    __shared__ float pw[TOPK];
    if (tid < TOPK) { pj[tid] = g_t2p[t * TOPK + tid]; pw[tid] = g_topw[t * TOPK + tid]; }
    __syncthreads();
    #pragma unroll
    for (int h = 0; h < 2; h++) {
        int c = h * 1024 + tid * 4;
        float4 acc = make_float4(0.f, 0.f, 0.f, 0.f);
        #pragma unroll
        for (int k = 0; k < TOPK; k++) {
            const float4 v = *(const float4*)(g_eout + (size_t)pj[k] * HIDDEN + c);
            float w = pw[k];
            acc.x += w * v.x; acc.y += w * v.y; acc.z += w * v.z; acc.w += w * v.w;
        }
        *(float4*)(y + (size_t)t * HIDDEN + c) = acc;
    }
}

// ================= E1 =================
// smem: toks @0 (256B) | A x3 @256 (3 x 10240) | B x2 @30976 (2 x (G8448+U8448))
#define E1_A    256
#define E1_B    30976
#define E1_BSZ  16896
#define E1_SMEM 64768
#define E1_NIT  (HIDDEN / 32)

extern __shared__ __align__(16) char dsm[];

__device__ __forceinline__ void e1_prefA(int tid, const int* toks, uint32_t sb,
                                         int k0, uint32_t abuf) {
    int m = tid >> 2, c4 = tid & 3;
    int t = toks[m];
    int zf = (t >= 0) ? 16 : 0;
    size_t so = (size_t)(t >= 0 ? t : 0) * HIDDEN + k0 + c4 * 8;
    uint32_t d = sb + E1_A + abuf + m * 80 + c4 * 16;
    cpa16z(d, g_x_hi + so, zf);
    cpa16z(d + 5120, g_x_lo + so, zf);
    CP_COMMIT();
}

__global__ __launch_bounds__(256, 3)
void e1_kernel(const float* __restrict__ gate_proj,
               const float* __restrict__ up_proj) {
    int e = blockIdx.x;
    int n = g_cnt[e];
    int mbase = blockIdx.y * 64;
    if (mbase >= n) return;
    int off = g_off[e];
    int nbase = blockIdx.z * 64;

    uint32_t sb = smem_u32(dsm);
    int tid = threadIdx.x, wid = tid >> 5, lane = tid & 31;
    int* toks = (int*)dsm;
    if (tid < 64) { int m = mbase + tid; toks[tid] = (m < n) ? g_pt[off + m] : -1; }
    __syncthreads();

    const float* gp  = gate_proj + (size_t)e * HIDDEN * INTER + nbase;
    const float* up_ = up_proj   + (size_t)e * HIDDEN * INTER + nbase;

    int wm = wid >> 2, wn = wid & 3;
    int g = lane >> 2, tg = lane & 3;
    int lq = lane >> 3, lr = lane & 7;
    int lmoff = ((lq & 1) * 8 + lr) * (AS * 2) + (lq >> 1) * 16;

    int nn2 = tid & 31, kg = tid >> 5;     // n-pair id, k-group

    float accg[2][2][4] = {};
    float accu[2][2][4] = {};
    float2 gv2[2][2], uv2[2][2];

    // weight LDG (consumed one iter later by convert)
    auto ldw = [&](int k0) {
        #pragma unroll
        for (int kpi = 0; kpi < 2; kpi++) {
            int k = (kpi * 8 + kg) * 2;
            const float* pg = gp + (size_t)(k0 + k) * INTER + nn2 * 2;
            const float* pu = up_ + (size_t)(k0 + k) * INTER + nn2 * 2;
            gv2[kpi][0] = *(const float2*)pg;
            gv2[kpi][1] = *(const float2*)(pg + INTER);
            uv2[kpi][0] = *(const float2*)pu;
            uv2[kpi][1] = *(const float2*)(pu + INTER);
        }
    };
    // convert regs -> B buffer (layout [r][c][n]{hi,lo}, 16B per n-pair)
    auto conv = [&](uint32_t bp_dst) {
        #pragma unroll
        for (int kpi = 0; kpi < 2; kpi++) {
            int kp = kpi * 8 + kg;
            int r = (kp & 3) | ((kp >> 3) << 2);
            int c = (kp >> 2) & 1;
            char* base = dsm + E1_B + bp_dst + r * GB_ROW + c * GB_HALF + nn2 * 16;
            uint4 o;
            split2t(gv2[kpi][0].x, gv2[kpi][1].x, o.x, o.y);
            split2t(gv2[kpi][0].y, gv2[kpi][1].y, o.z, o.w);
            *(uint4*)base = o;
            split2t(uv2[kpi][0].x, uv2[kpi][1].x, o.x, o.y);
            split2t(uv2[kpi][0].y, uv2[kpi][1].y, o.z, o.w);
            *(uint4*)(base + 8448) = o;
        }
    };

    // prologue
    ldw(0);
    e1_prefA(tid, toks, sb, 0, 0);
    conv(0);
    ldw(32);
    e1_prefA(tid, toks, sb, 32, 10240);
    CP_WAIT1();
    __syncthreads();

    uint32_t ap_r = 0, ap_w = 20480, bp = 0;
    for (int it = 0; it < E1_NIT; it++) {
        // ---- MMA(it): A[ap_r], B[bp] ----
        uint32_t Ah_base = sb + E1_A + ap_r + (wm * 32) * 80 + lmoff;
        #pragma unroll
        for (int kk = 0; kk < 32; kk += 16) {
            uint32_t ah[2][4], al[2][4];
            #pragma unroll
            for (int mf = 0; mf < 2; mf++) {
                uint32_t aaddr = Ah_base + mf * (16 * 80) + kk * 2;
                ldsm4(ah[mf], aaddr);
                ldsm4(al[mf], aaddr + 5120);
            }
            const char* Grow = dsm + E1_B + bp + (tg + (kk >> 2)) * GB_ROW;
            {
                uint32_t bh[2][2], bl[2][2];
                #pragma unroll
                for (int nf = 0; nf < 2; nf++) {
                    int nb = (wn * 16 + nf * 8 + g) * 8;
                    uint2 v0 = *(const uint2*)(Grow + nb);
                    uint2 v1 = *(const uint2*)(Grow + GB_HALF + nb);
                    bh[nf][0] = v0.x; bl[nf][0] = v0.y;
                    bh[nf][1] = v1.x; bl[nf][1] = v1.y;
                }
                #pragma unroll
                for (int mf = 0; mf < 2; mf++)
                #pragma unroll
                for (int nf = 0; nf < 2; nf++) {
                    mma16816(accg[mf][nf], ah[mf], bh[nf]);
                    mma16816(accg[mf][nf], ah[mf], bl[nf]);
                    mma16816(accg[mf][nf], al[mf], bh[nf]);
                }
            }
            {
                const char* Urow = Grow + 8448;
                uint32_t bh[2][2], bl[2][2];
                #pragma unroll
                for (int nf = 0; nf < 2; nf++) {
                    int nb = (wn * 16 + nf * 8 + g) * 8;
                    uint2 v0 = *(const uint2*)(Urow + nb);
                    uint2 v1 = *(const uint2*)(Urow + GB_HALF + nb);
                    bh[nf][0] = v0.x; bl[nf][0] = v0.y;
                    bh[nf][1] = v1.x; bl[nf][1] = v1.y;
                }
                #pragma unroll
                for (int mf = 0; mf < 2; mf++)
                #pragma unroll
                for (int nf = 0; nf < 2; nf++) {
                    mma16816(accu[mf][nf], ah[mf], bh[nf]);
                    mma16816(accu[mf][nf], ah[mf], bl[nf]);
                    mma16816(accu[mf][nf], al[mf], bh[nf]);
                }
            }
        }

        // ---- convert(it+1) into other B buffer (overlaps tensor drain) ----
        if (it + 1 < E1_NIT) conv(bp ^ E1_BSZ);
        // ---- prefetch it+2 ----
        if (it + 2 < E1_NIT) {
            ldw((it + 2) * 32);
            e1_prefA(tid, toks, sb, (it + 2) * 32, ap_w);
            CP_WAIT1();
        } else if (it + 1 < E1_NIT) {
            CP_WAIT0();
        }
        __syncthreads();
        bp ^= E1_BSZ;
        ap_r = (ap_r == 20480) ? 0 : ap_r + 10240;
        ap_w = (ap_w == 20480) ? 0 : ap_w + 10240;
    }

    // ---- epilogue: silu(g)*u -> split bf16 -> g_act (packed 4B stores) ----
    #pragma unroll
    for (int mf = 0; mf < 2; mf++)
    #pragma unroll
    for (int nf = 0; nf < 2; nf++)
    #pragma unroll
    for (int half = 0; half < 2; half++) {
        int m = mbase + wm * 32 + mf * 16 + g + half * 8;
        if (m >= n) continue;
        int col = nbase + wn * 16 + nf * 8 + 2 * tg;
        float g0 = accg[mf][nf][half * 2],     u0 = accu[mf][nf][half * 2];
        float g1 = accg[mf][nf][half * 2 + 1], u1 = accu[mf][nf][half * 2 + 1];
        float a0 = (g0 / (1.f + __expf(-g0))) * u0;
        float a1 = (g1 / (1.f + __expf(-g1))) * u1;
        uint32_t hi, lo;
        split2t(a0, a1, hi, lo);
        size_t ai = (size_t)(off + m) * INTER + col;
        *(uint32_t*)&g_act_hi[ai] = hi;
        *(uint32_t*)&g_act_lo[ai] = lo;
    }
}

// ================= E2 (M64 x N128) =================
// smem: A x3 @0 (3 x 10240) | B x2 @30720 (2 x 16640)
#define E2_A    0
#define E2_B    30720
#define E2_BSZ  16640
#define E2_SMEM 64000
#define E2_NIT  (INTER / 32)

__device__ __forceinline__ void e2_prefA(int tid, int off, int mbase, int n, uint32_t sb,
                                         int k0, uint32_t abuf) {
    int m = tid >> 2, c4 = tid & 3;
    bool valid = (mbase + m) < n;
    int zf = valid ? 16 : 0;
    size_t so = valid ? ((size_t)(off + mbase + m) * INTER + k0 + c4 * 8) : 0;
    uint32_t d = sb + E2_A + abuf + m * 80 + c4 * 16;
    cpa16z(d, g_act_hi + so, zf);
    cpa16z(d + 5120, g_act_lo + so, zf);
    CP_COMMIT();
}

__global__ __launch_bounds__(256, 3)
void e2_kernel(const float* __restrict__ down_proj) {
    int e = blockIdx.x;
    int n = g_cnt[e];
    int mbase = blockIdx.y * 64;
    if (mbase >= n) return;
    int off = g_off[e];
    int nbase = blockIdx.z * 128;

    uint32_t sb = smem_u32(dsm);
    int tid = threadIdx.x, wid = tid >> 5, lane = tid & 31;
    int wm = wid >> 2, wn = wid & 3;
    int g = lane >> 2, tg = lane & 3;
    int lq = lane >> 3, lr = lane & 7;
    int lmoff = ((lq & 1) * 8 + lr) * (AS * 2) + (lq >> 1) * 16;

    int nn2 = tid & 63, kg = tid >> 6;

    const float* dp = down_proj + (size_t)e * INTER * HIDDEN + nbase;

    float acc[2][4][4] = {};
    float2 bv2[4][2];

    auto ldw = [&](int k0) {
        #pragma unroll
        for (int kpi = 0; kpi < 4; kpi++) {
            int k = (kpi * 4 + kg) * 2;
            const float* pb = dp + (size_t)(k0 + k) * HIDDEN + nn2 * 2;
            bv2[kpi][0] = *(const float2*)pb;
            bv2[kpi][1] = *(const float2*)(pb + HIDDEN);
        }
    };
    auto conv = [&](uint32_t bp_dst) {
        #pragma unroll
        for (int kpi = 0; kpi < 4; kpi++) {
            int kp = kpi * 4 + kg;
            int r = (kp & 3) | ((kp >> 3) << 2);
            int c = (kp >> 2) & 1;
            char* base = dsm + E2_B + bp_dst + r * GB_ROW2 + c * GB_HALF2 + nn2 * 16;
            uint4 o;
            split2t(bv2[kpi][0].x, bv2[kpi][1].x, o.x, o.y);
            split2t(bv2[kpi][0].y, bv2[kpi][1].y, o.z, o.w);
            *(uint4*)base = o;
        }
    };

    ldw(0);
    e2_prefA(tid, off, mbase, n, sb, 0, 0);
    conv(0);
    ldw(32);
    e2_prefA(tid, off, mbase, n, sb, 32, 10240);
    CP_WAIT1();
    __syncthreads();

    uint32_t ap_r = 0, ap_w = 20480, bp = 0;
    for (int it = 0; it < E2_NIT; it++) {
        uint32_t Ah_base = sb + E2_A + ap_r + (wm * 32) * 80 + lmoff;
        #pragma unroll
        for (int kk = 0; kk < 32; kk += 16) {
            uint32_t ah[2][4], al[2][4];
            #pragma unroll
            for (int mf = 0; mf < 2; mf++) {
                uint32_t aaddr = Ah_base + mf * (16 * 80) + kk * 2;
                ldsm4(ah[mf], aaddr);
                ldsm4(al[mf], aaddr + 5120);
            }
            const char* Brow = dsm + E2_B + bp + (tg + (kk >> 2)) * GB_ROW2;
            uint32_t bh[4][2], bl[4][2];
            #pragma unroll
            for (int nf = 0; nf < 4; nf++) {
                int nb = (wn * 32 + nf * 8 + g) * 8;
                uint2 v0 = *(const uint2*)(Brow + nb);
                uint2 v1 = *(const uint2*)(Brow + GB_HALF2 + nb);
                bh[nf][0] = v0.x; bl[nf][0] = v0.y;
                bh[nf][1] = v1.x; bl[nf][1] = v1.y;
            }
            #pragma unroll
            for (int mf = 0; mf < 2; mf++)
            #pragma unroll
            for (int nf = 0; nf < 4; nf++) {
                mma16816(acc[mf][nf], ah[mf], bh[nf]);
                mma16816(acc[mf][nf], ah[mf], bl[nf]);
                mma16816(acc[mf][nf], al[mf], bh[nf]);
            }
        }

        if (it + 1 < E2_NIT) conv(bp ^ E2_BSZ);
        if (it + 2 < E2_NIT) {
            ldw((it + 2) * 32);
            e2_prefA(tid, off, mbase, n, sb, (it + 2) * 32, ap_w);
            CP_WAIT1();
        } else if (it + 1 < E2_NIT) {
            CP_WAIT0();
        }
        __syncthreads();
        bp ^= E2_BSZ;
        ap_r = (ap_r == 20480) ? 0 : ap_r + 10240;
        ap_w = (ap_w == 20480) ? 0 : ap_w + 10240;
    }

    // ---- epilogue: raw per-pair output rows ----
    #pragma unroll
    for (int mf = 0; mf < 2; mf++) {
        #pragma unroll
        for (int half = 0; half < 2; half++) {
            int m = mbase + wm * 32 + mf * 16 + g + half * 8;
            if (m >= n) continue;
            float* orow = g_eout + (size_t)(off + m) * HIDDEN + nbase;
            #pragma unroll
            for (int nf = 0; nf < 4; nf++) {
                int col = wn * 32 + nf * 8 + 2 * tg;
                float2 v = make_float2(acc[mf][nf][half * 2], acc[mf][nf][half * 2 + 1]);
                *(float2*)&orow[col] = v;
            }
        }
    }
}

// ================= launch =================
extern "C" void kernel_launch(void* const* d_in, const int* in_sizes, int n_in,
                              void* d_out, int out_size) {
    const float* x  = (const float*)d_in[0];
    const float* gw = (const float*)d_in[1];
    const float* gp = (const float*)d_in[2];
    const float* up = (const float*)d_in[3];
    const float* dp = (const float*)d_in[4];
    float* y = (float*)d_out;

    int T = in_sizes[0] / HIDDEN;
    int nTot = T * HIDDEN;

    cudaFuncSetAttribute(e1_kernel, cudaFuncAttributeMaxDynamicSharedMemorySize, E1_SMEM);
    cudaFuncSetAttribute(e2_kernel, cudaFuncAttributeMaxDynamicSharedMemorySize, E2_SMEM);

    prep_x_kernel<<<(nTot / 4 + 255) / 256, 256>>>(x, nTot);
    router_kernel<<<T, 128>>>(x, gw);
    build_kernel<<<1, 512>>>(T);

    dim3 g1(NE, (T + 63) / 64, INTER / 64);    // (32, 8, 12)
    e1_kernel<<<g1, 256, E1_SMEM>>>(gp, up);

    dim3 g2(NE, (T + 63) / 64, HIDDEN / 128);  // (32, 8, 16)
    e2_kernel<<<g2, 256, E2_SMEM>>>(dp);

    combine_kernel<<<T, 256>>>(y);
}

// round 12
// speedup vs baseline: 1.1298x; 1.1298x over previous
#include <cuda_runtime.h>
#include <cuda_bf16.h>
#include <math.h>
#include <stdint.h>

#define HIDDEN 2048
#define INTER  768
#define NE     32
#define TOPK   8
#define MAXT   512
#define MAXP   (MAXT * TOPK)

typedef unsigned short ushort_t;

// ---- scratch (device globals) ----
__device__ float g_topw[MAXP];
__device__ int   g_topi[MAXP];
__device__ int   g_cnt[NE];
__device__ int   g_off[NE];
__device__ int   g_pt[MAXP];
__device__ int   g_t2p[MAXP];
__device__ ushort_t g_x_hi[(size_t)MAXT * HIDDEN];
__device__ ushort_t g_x_lo[(size_t)MAXT * HIDDEN];
__device__ ushort_t g_act_hi[(size_t)MAXP * INTER];
__device__ ushort_t g_act_lo[(size_t)MAXP * INTER];
__device__ float g_eout[(size_t)MAXP * HIDDEN];

// ================= helpers =================
__device__ __forceinline__ uint32_t smem_u32(const void* p) {
    uint32_t a;
    asm("{ .reg .u64 t; cvta.to.shared.u64 t, %1; cvt.u32.u64 %0, t; }" : "=r"(a) : "l"(p));
    return a;
}
__device__ __forceinline__ void cpa16z(uint32_t dst, const void* src, int zf) {
    asm volatile("cp.async.ca.shared.global [%0], [%1], 16, %2;" :: "r"(dst), "l"(src), "r"(zf));
}
#define CP_COMMIT() asm volatile("cp.async.commit_group;" ::: "memory")
#define CP_WAIT0()  asm volatile("cp.async.wait_group 0;" ::: "memory")
#define CP_WAIT1()  asm volatile("cp.async.wait_group 1;" ::: "memory")

__device__ __forceinline__ void ldsm4(uint32_t* r, uint32_t addr) {
    asm volatile("ldmatrix.sync.aligned.m8n8.x4.shared.b16 {%0,%1,%2,%3}, [%4];"
        : "=r"(r[0]), "=r"(r[1]), "=r"(r[2]), "=r"(r[3]) : "r"(addr));
}

__device__ __forceinline__ unsigned short bfh(float v) { return __bfloat16_as_ushort(__float2bfloat16(v)); }

// cheap split: hi = truncated top-16 bits (exact residual), lo = RN-bf16 of residual
__device__ __forceinline__ void split2t(float a, float b, uint32_t& hi, uint32_t& lo) {
    uint32_t ua = __float_as_uint(a), ub = __float_as_uint(b);
    hi = __byte_perm(ua, ub, 0x7632);
    float ra = a - __uint_as_float(ua & 0xFFFF0000u);
    float rb = b - __uint_as_float(ub & 0xFFFF0000u);
    asm("cvt.rn.bf16x2.f32 %0, %1, %2;" : "=r"(lo) : "f"(rb), "f"(ra));
}

__device__ __forceinline__ void mma16816(float* c, const uint32_t* a, const uint32_t* b) {
    asm volatile(
        "mma.sync.aligned.m16n8k16.row.col.f32.bf16.bf16.f32 "
        "{%0,%1,%2,%3}, {%4,%5,%6,%7}, {%8,%9}, {%0,%1,%2,%3};"
        : "+f"(c[0]), "+f"(c[1]), "+f"(c[2]), "+f"(c[3])
        : "r"(a[0]), "r"(a[1]), "r"(a[2]), "r"(a[3]), "r"(b[0]), "r"(b[1]));
}

#define AS 40        // A smem row stride (ushorts); 80B rows
#define GB_ROW 1056  // e1 B row stride bytes
#define GB_HALF 512
#define GB_ROW2 2080 // e2 B row stride bytes
#define GB_HALF2 1024

// ================= small kernels =================
__global__ void prep_x_kernel(const float* __restrict__ x, int nTot) {
    int i = (blockIdx.x * 256 + threadIdx.x) * 4;
    if (i < nTot) {
        float4 v = *(const float4*)(x + i);
        uint2 H, L;
        split2t(v.x, v.y, H.x, L.x);
        split2t(v.z, v.w, H.y, L.y);
        *(uint2*)&g_x_hi[i] = H;
        *(uint2*)&g_x_lo[i] = L;
    }
}

__global__ void router_kernel(const float* __restrict__ x, const float* __restrict__ gw) {
    int t = blockIdx.x;
    __shared__ float xs[HIDDEN];
    __shared__ float logits[NE];
    int tid = threadIdx.x;
    for (int i = tid; i < HIDDEN; i += 128) xs[i] = x[(size_t)t * HIDDEN + i];
    __syncthreads();
    int warp = tid >> 5, lane = tid & 31;
    for (int e8 = 0; e8 < 8; e8++) {
        int e = warp * 8 + e8;
        const float* w = gw + (size_t)e * HIDDEN;
        float s = 0.f;
        for (int h = lane; h < HIDDEN; h += 32) s += xs[h] * w[h];
        #pragma unroll
        for (int o = 16; o; o >>= 1) s += __shfl_xor_sync(0xffffffffu, s, o);
        if (lane == 0) logits[e] = s;
    }
    __syncthreads();
    if (tid == 0) {
        float mx = -1e30f;
        for (int e = 0; e < NE; e++) mx = fmaxf(mx, logits[e]);
        float p[NE];
        for (int e = 0; e < NE; e++) p[e] = expf(logits[e] - mx);
        bool used[NE] = {};
        float wsum = 0.f; int idx[TOPK]; float wv[TOPK];
        for (int k = 0; k < TOPK; k++) {
            float best = -1.f; int bi = 0;
            for (int e = 0; e < NE; e++)
                if (!used[e] && p[e] > best) { best = p[e]; bi = e; }
            used[bi] = true; idx[k] = bi; wv[k] = best; wsum += best;
        }
        float inv = 1.f / wsum;
        for (int k = 0; k < TOPK; k++) {
            g_topi[t * TOPK + k] = idx[k];
            g_topw[t * TOPK + k] = wv[k] * inv;
        }
    }
}

__global__ void build_kernel(int T) {
    __shared__ int cnt[NE], cur[NE];
    int tid = threadIdx.x;
    int np = T * TOPK;
    if (tid < NE) cnt[tid] = 0;
    __syncthreads();
    for (int p = tid; p < np; p += blockDim.x) atomicAdd(&cnt[g_topi[p]], 1);
    __syncthreads();
    if (tid == 0) {
        int off = 0;
        for (int e = 0; e < NE; e++) {
            g_off[e] = off; g_cnt[e] = cnt[e]; cur[e] = off; off += cnt[e];
        }
    }
    __syncthreads();
    for (int p = tid; p < np; p += blockDim.x) {
        int e = g_topi[p];
        int j = atomicAdd(&cur[e], 1);
        g_pt[j] = p >> 3;
        g_t2p[p] = j;
    }
}

__global__ void combine_kernel(float* __restrict__ y) {
    int t = blockIdx.x, tid = threadIdx.x;
    __shared__ int   pj[TOPK];
    __shared__ float pw[TOPK];
    if (tid < TOPK) { pj[tid] = g_t2p[t * TOPK + tid]; pw[tid] = g_topw[t * TOPK + tid]; }
    __syncthreads();
    #pragma unroll
    for (int h = 0; h < 2; h++) {
        int c = h * 1024 + tid * 4;
        float4 acc = make_float4(0.f, 0.f, 0.f, 0.f);
        #pragma unroll
        for (int k = 0; k < TOPK; k++) {
            const float4 v = *(const float4*)(g_eout + (size_t)pj[k] * HIDDEN + c);
            float w = pw[k];
            acc.x += w * v.x; acc.y += w * v.y; acc.z += w * v.z; acc.w += w * v.w;
        }
        *(float4*)(y + (size_t)t * HIDDEN + c) = acc;
    }
}

// ================= E1 (M128 x N64(g)+N64(u), 512 threads) =================
// smem: toks @0 (512B) | A x3 @512 (3 x 20480, hi/lo halves of 10240) |
//       B x2 @61952 (2 x (G8448+U8448))
#define E1_A    512
#define E1_ABUF 20480
#define E1_B    61952
#define E1_BSZ  16896
#define E1_SMEM 95744
#define E1_NIT  (HIDDEN / 32)

extern __shared__ __align__(16) char dsm[];

__device__ __forceinline__ void e1_prefA(int tid, const int* toks, uint32_t sb,
                                         int k0, uint32_t abuf) {
    int m = tid >> 2, c4 = tid & 3;
    int t = toks[m];
    int zf = (t >= 0) ? 16 : 0;
    size_t so = (size_t)(t >= 0 ? t : 0) * HIDDEN + k0 + c4 * 8;
    uint32_t d = sb + E1_A + abuf + m * 80 + c4 * 16;
    cpa16z(d, g_x_hi + so, zf);
    cpa16z(d + 10240, g_x_lo + so, zf);
    CP_COMMIT();
}

__global__ __launch_bounds__(512, 1)
void e1_kernel(const float* __restrict__ gate_proj,
               const float* __restrict__ up_proj) {
    int e = blockIdx.x;
    int n = g_cnt[e];
    int mbase = blockIdx.y * 128;
    if (mbase >= n) return;
    int off = g_off[e];
    int nbase = blockIdx.z * 64;

    uint32_t sb = smem_u32(dsm);
    int tid = threadIdx.x, wid = tid >> 5, lane = tid & 31;
    int* toks = (int*)dsm;
    if (tid < 128) { int m = mbase + tid; toks[tid] = (m < n) ? g_pt[off + m] : -1; }
    __syncthreads();

    const float* gp  = gate_proj + (size_t)e * HIDDEN * INTER + nbase;
    const float* up_ = up_proj   + (size_t)e * HIDDEN * INTER + nbase;

    int wm = wid >> 2, wn = wid & 3;           // 4m x 4n warps
    int g = lane >> 2, tg = lane & 3;
    int lq = lane >> 3, lr = lane & 7;
    int lmoff = ((lq & 1) * 8 + lr) * (AS * 2) + (lq >> 1) * 16;

    int nn2 = tid & 31, kg = tid >> 5;         // n-pair id (32), kp id (16)

    float accg[2][2][4] = {};
    float accu[2][2][4] = {};
    float2 gv2[2], uv2[2];

    // weight LDG: 1 k-pair per thread (kg = kp)
    auto ldw = [&](int k0) {
        int k = kg * 2;
        const float* pg = gp + (size_t)(k0 + k) * INTER + nn2 * 2;
        const float* pu = up_ + (size_t)(k0 + k) * INTER + nn2 * 2;
        gv2[0] = *(const float2*)pg;
        gv2[1] = *(const float2*)(pg + INTER);
        uv2[0] = *(const float2*)pu;
        uv2[1] = *(const float2*)(pu + INTER);
    };
    // convert regs -> B buffer (layout [r][c][n]{hi,lo}, 16B per n-pair)
    auto conv = [&](uint32_t bp_dst) {
        int kp = kg;
        int r = (kp & 3) | ((kp >> 3) << 2);
        int c = (kp >> 2) & 1;
        char* base = dsm + E1_B + bp_dst + r * GB_ROW + c * GB_HALF + nn2 * 16;
        uint4 o;
        split2t(gv2[0].x, gv2[1].x, o.x, o.y);
        split2t(gv2[0].y, gv2[1].y, o.z, o.w);
        *(uint4*)base = o;
        split2t(uv2[0].x, uv2[1].x, o.x, o.y);
        split2t(uv2[0].y, uv2[1].y, o.z, o.w);
        *(uint4*)(base + 8448) = o;
    };

    // prologue
    ldw(0);
    e1_prefA(tid, toks, sb, 0, 0);
    conv(0);
    ldw(32);
    e1_prefA(tid, toks, sb, 32, E1_ABUF);
    CP_WAIT1();
    __syncthreads();

    uint32_t ap_r = 0, ap_w = 2 * E1_ABUF, bp = 0;
    for (int it = 0; it < E1_NIT; it++) {
        // ---- MMA(it): A[ap_r], B[bp] ----
        uint32_t Ah_base = sb + E1_A + ap_r + (wm * 32) * 80 + lmoff;
        #pragma unroll
        for (int kk = 0; kk < 32; kk += 16) {
            uint32_t ah[2][4], al[2][4];
            #pragma unroll
            for (int mf = 0; mf < 2; mf++) {
                uint32_t aaddr = Ah_base + mf * (16 * 80) + kk * 2;
                ldsm4(ah[mf], aaddr);
                ldsm4(al[mf], aaddr + 10240);
            }
            const char* Grow = dsm + E1_B + bp + (tg + (kk >> 2)) * GB_ROW;
            {
                uint32_t bh[2][2], bl[2][2];
                #pragma unroll
                for (int nf = 0; nf < 2; nf++) {
                    int nb = (wn * 16 + nf * 8 + g) * 8;
                    uint2 v0 = *(const uint2*)(Grow + nb);
                    uint2 v1 = *(const uint2*)(Grow + GB_HALF + nb);
                    bh[nf][0] = v0.x; bl[nf][0] = v0.y;
                    bh[nf][1] = v1.x; bl[nf][1] = v1.y;
                }
                #pragma unroll
                for (int mf = 0; mf < 2; mf++)
                #pragma unroll
                for (int nf = 0; nf < 2; nf++) {
                    mma16816(accg[mf][nf], ah[mf], bh[nf]);
                    mma16816(accg[mf][nf], ah[mf], bl[nf]);
                    mma16816(accg[mf][nf], al[mf], bh[nf]);
                }
            }
            {
                const char* Urow = Grow + 8448;
                uint32_t bh[2][2], bl[2][2];
                #pragma unroll
                for (int nf = 0; nf < 2; nf++) {
                    int nb = (wn * 16 + nf * 8 + g) * 8;
                    uint2 v0 = *(const uint2*)(Urow + nb);
                    uint2 v1 = *(const uint2*)(Urow + GB_HALF + nb);
                    bh[nf][0] = v0.x; bl[nf][0] = v0.y;
                    bh[nf][1] = v1.x; bl[nf][1] = v1.y;
                }
                #pragma unroll
                for (int mf = 0; mf < 2; mf++)
                #pragma unroll
                for (int nf = 0; nf < 2; nf++) {
                    mma16816(accu[mf][nf], ah[mf], bh[nf]);
                    mma16816(accu[mf][nf], ah[mf], bl[nf]);
                    mma16816(accu[mf][nf], al[mf], bh[nf]);
                }
            }
        }

        // ---- convert(it+1) into other B buffer ----
        if (it + 1 < E1_NIT) conv(bp ^ E1_BSZ);
        // ---- prefetch it+2 ----
        if (it + 2 < E1_NIT) {
            ldw((it + 2) * 32);
            e1_prefA(tid, toks, sb, (it + 2) * 32, ap_w);
            CP_WAIT1();
        } else if (it + 1 < E1_NIT) {
            CP_WAIT0();
        }
        __syncthreads();
        bp ^= E1_BSZ;
        ap_r = (ap_r == 2 * E1_ABUF) ? 0 : ap_r + E1_ABUF;
        ap_w = (ap_w == 2 * E1_ABUF) ? 0 : ap_w + E1_ABUF;
    }

    // ---- epilogue: silu(g)*u -> split bf16 -> g_act (packed 4B stores) ----
    #pragma unroll
    for (int mf = 0; mf < 2; mf++)
    #pragma unroll
    for (int nf = 0; nf < 2; nf++)
    #pragma unroll
    for (int half = 0; half < 2; half++) {
        int m = mbase + wm * 32 + mf * 16 + g + half * 8;
        if (m >= n) continue;
        int col = nbase + wn * 16 + nf * 8 + 2 * tg;
        float g0 = accg[mf][nf][half * 2],     u0 = accu[mf][nf][half * 2];
        float g1 = accg[mf][nf][half * 2 + 1], u1 = accu[mf][nf][half * 2 + 1];
        float a0 = (g0 / (1.f + __expf(-g0))) * u0;
        float a1 = (g1 / (1.f + __expf(-g1))) * u1;
        uint32_t hi, lo;
        split2t(a0, a1, hi, lo);
        size_t ai = (size_t)(off + m) * INTER + col;
        *(uint32_t*)&g_act_hi[ai] = hi;
        *(uint32_t*)&g_act_lo[ai] = lo;
    }
}

// ================= E2 (M128 x N128, 512 threads) =================
// smem: A x3 @0 (3 x 20480) | B x2 @61440 (2 x 16640)
#define E2_A    0
#define E2_ABUF 20480
#define E2_B    61440
#define E2_BSZ  16640
#define E2_SMEM 94720
#define E2_NIT  (INTER / 32)

__device__ __forceinline__ void e2_prefA(int tid, int off, int mbase, int n, uint32_t sb,
                                         int k0, uint32_t abuf) {
    int m = tid >> 2, c4 = tid & 3;
    bool valid = (mbase + m) < n;
    int zf = valid ? 16 : 0;
    size_t so = valid ? ((size_t)(off + mbase + m) * INTER + k0 + c4 * 8) : 0;
    uint32_t d = sb + E2_A + abuf + m * 80 + c4 * 16;
    cpa16z(d, g_act_hi + so, zf);
    cpa16z(d + 10240, g_act_lo + so, zf);
    CP_COMMIT();
}

__global__ __launch_bounds__(512, 1)
void e2_kernel(const float* __restrict__ down_proj) {
    int e = blockIdx.x;
    int n = g_cnt[e];
    int mbase = blockIdx.y * 128;
    if (mbase >= n) return;
    int off = g_off[e];
    int nbase = blockIdx.z * 128;

    uint32_t sb = smem_u32(dsm);
    int tid = threadIdx.x, wid = tid >> 5, lane = tid & 31;
    int wm = wid >> 2, wn = wid & 3;           // 4m x 4n warps
    int g = lane >> 2, tg = lane & 3;
    int lq = lane >> 3, lr = lane & 7;
    int lmoff = ((lq & 1) * 8 + lr) * (AS * 2) + (lq >> 1) * 16;

    int nn2 = tid & 63, kg = tid >> 6;         // n-pair (64), k-group (8)

    const float* dp = down_proj + (size_t)e * INTER * HIDDEN + nbase;

    float acc[2][4][4] = {};
    float2 bv2[2][2];

    auto ldw = [&](int k0) {
        #pragma unroll
        for (int kpi = 0; kpi < 2; kpi++) {
            int k = (kpi * 8 + kg) * 2;
            const float* pb = dp + (size_t)(k0 + k) * HIDDEN + nn2 * 2;
            bv2[kpi][0] = *(const float2*)pb;
            bv2[kpi][1] = *(const float2*)(pb + HIDDEN);
        }
    };
    auto conv = [&](uint32_t bp_dst) {
        #pragma unroll
        for (int kpi = 0; kpi < 2; kpi++) {
            int kp = kpi * 8 + kg;
            int r = (kp & 3) | ((kp >> 3) << 2);
            int c = (kp >> 2) & 1;
            char* base = dsm + E2_B + bp_dst + r * GB_ROW2 + c * GB_HALF2 + nn2 * 16;
            uint4 o;
            split2t(bv2[kpi][0].x, bv2[kpi][1].x, o.x, o.y);
            split2t(bv2[kpi][0].y, bv2[kpi][1].y, o.z, o.w);
            *(uint4*)base = o;
        }
    };

    ldw(0);
    e2_prefA(tid, off, mbase, n, sb, 0, 0);
    conv(0);
    ldw(32);
    e2_prefA(tid, off, mbase, n, sb, 32, E2_ABUF);
    CP_WAIT1();
    __syncthreads();

    uint32_t ap_r = 0, ap_w = 2 * E2_ABUF, bp = 0;
    for (int it = 0; it < E2_NIT; it++) {
        uint32_t Ah_base = sb + E2_A + ap_r + (wm * 32) * 80 + lmoff;
        #pragma unroll
        for (int kk = 0; kk < 32; kk += 16) {
            uint32_t ah[2][4], al[2][4];
            #pragma unroll
            for (int mf = 0; mf < 2; mf++) {
                uint32_t aaddr = Ah_base + mf * (16 * 80) + kk * 2;
                ldsm4(ah[mf], aaddr);
                ldsm4(al[mf], aaddr + 10240);
            }
            const char* Brow = dsm + E2_B + bp + (tg + (kk >> 2)) * GB_ROW2;
            uint32_t bh[4][2], bl[4][2];
            #pragma unroll
            for (int nf = 0; nf < 4; nf++) {
                int nb = (wn * 32 + nf * 8 + g) * 8;
                uint2 v0 = *(const uint2*)(Brow + nb);
                uint2 v1 = *(const uint2*)(Brow + GB_HALF2 + nb);
                bh[nf][0] = v0.x; bl[nf][0] = v0.y;
                bh[nf][1] = v1.x; bl[nf][1] = v1.y;
            }
            #pragma unroll
            for (int mf = 0; mf < 2; mf++)
            #pragma unroll
            for (int nf = 0; nf < 4; nf++) {
                mma16816(acc[mf][nf], ah[mf], bh[nf]);
                mma16816(acc[mf][nf], ah[mf], bl[nf]);
                mma16816(acc[mf][nf], al[mf], bh[nf]);
            }
        }

        if (it + 1 < E2_NIT) conv(bp ^ E2_BSZ);
        if (it + 2 < E2_NIT) {
            ldw((it + 2) * 32);
            e2_prefA(tid, off, mbase, n, sb, (it + 2) * 32, ap_w);
            CP_WAIT1();
        } else if (it + 1 < E2_NIT) {
            CP_WAIT0();
        }
        __syncthreads();
        bp ^= E2_BSZ;
        ap_r = (ap_r == 2 * E2_ABUF) ? 0 : ap_r + E2_ABUF;
        ap_w = (ap_w == 2 * E2_ABUF) ? 0 : ap_w + E2_ABUF;
    }

    // ---- epilogue: raw per-pair output rows ----
    #pragma unroll
    for (int mf = 0; mf < 2; mf++) {
        #pragma unroll
        for (int half = 0; half < 2; half++) {
            int m = mbase + wm * 32 + mf * 16 + g + half * 8;
            if (m >= n) continue;
            float* orow = g_eout + (size_t)(off + m) * HIDDEN + nbase;
            #pragma unroll
            for (int nf = 0; nf < 4; nf++) {
                int col = wn * 32 + nf * 8 + 2 * tg;
                float2 v = make_float2(acc[mf][nf][half * 2], acc[mf][nf][half * 2 + 1]);
                *(float2*)&orow[col] = v;
            }
        }
    }
}

// ================= launch =================
extern "C" void kernel_launch(void* const* d_in, const int* in_sizes, int n_in,
                              void* d_out, int out_size) {
    const float* x  = (const float*)d_in[0];
    const float* gw = (const float*)d_in[1];
    const float* gp = (const float*)d_in[2];
    const float* up = (const float*)d_in[3];
    const float* dp = (const float*)d_in[4];
    float* y = (float*)d_out;

    int T = in_sizes[0] / HIDDEN;
    int nTot = T * HIDDEN;

    cudaFuncSetAttribute(e1_kernel, cudaFuncAttributeMaxDynamicSharedMemorySize, E1_SMEM);
    cudaFuncSetAttribute(e2_kernel, cudaFuncAttributeMaxDynamicSharedMemorySize, E2_SMEM);

    prep_x_kernel<<<(nTot / 4 + 255) / 256, 256>>>(x, nTot);
    router_kernel<<<T, 128>>>(x, gw);
    build_kernel<<<1, 512>>>(T);

    dim3 g1(NE, (T + 127) / 128, INTER / 64);    // (32, 4, 12)
    e1_kernel<<<g1, 512, E1_SMEM>>>(gp, up);

    dim3 g2(NE, (T + 127) / 128, HIDDEN / 128);  // (32, 4, 16)
    e2_kernel<<<g2, 512, E2_SMEM>>>(dp);

    combine_kernel<<<T, 256>>>(y);
}

// round 13
// speedup vs baseline: 1.2328x; 1.0912x over previous
#include <cuda_runtime.h>
#include <cuda_bf16.h>
#include <math.h>
#include <stdint.h>

#define HIDDEN 2048
#define INTER  768
#define NE     32
#define TOPK   8
#define MAXT   512
#define MAXP   (MAXT * TOPK)

typedef unsigned short ushort_t;

// ---- scratch (device globals) ----
__device__ float g_topw[MAXP];
__device__ int   g_topi[MAXP];
__device__ int   g_cnt[NE];
__device__ int   g_off[NE];
__device__ int   g_pt[MAXP];
__device__ int   g_t2p[MAXP];
__device__ ushort_t g_x_hi[(size_t)MAXT * HIDDEN];
__device__ ushort_t g_x_lo[(size_t)MAXT * HIDDEN];
__device__ ushort_t g_act_hi[(size_t)MAXP * INTER];
__device__ ushort_t g_act_lo[(size_t)MAXP * INTER];
__device__ float g_eout[(size_t)MAXP * HIDDEN];

// ================= helpers =================
__device__ __forceinline__ uint32_t smem_u32(const void* p) {
    uint32_t a;
    asm("{ .reg .u64 t; cvta.to.shared.u64 t, %1; cvt.u32.u64 %0, t; }" : "=r"(a) : "l"(p));
    return a;
}
__device__ __forceinline__ void cpa16z(uint32_t dst, const void* src, int zf) {
    asm volatile("cp.async.ca.shared.global [%0], [%1], 16, %2;" :: "r"(dst), "l"(src), "r"(zf));
}
#define CP_COMMIT() asm volatile("cp.async.commit_group;" ::: "memory")
#define CP_WAIT0()  asm volatile("cp.async.wait_group 0;" ::: "memory")
#define CP_WAIT1()  asm volatile("cp.async.wait_group 1;" ::: "memory")

__device__ __forceinline__ void ldsm4(uint32_t* r, uint32_t addr) {
    asm volatile("ldmatrix.sync.aligned.m8n8.x4.shared.b16 {%0,%1,%2,%3}, [%4];"
        : "=r"(r[0]), "=r"(r[1]), "=r"(r[2]), "=r"(r[3]) : "r"(addr));
}

__device__ __forceinline__ unsigned short bfh(float v) { return __bfloat16_as_ushort(__float2bfloat16(v)); }

// cheap split: hi = truncated top-16 bits (exact residual), lo = RN-bf16 of residual
__device__ __forceinline__ void split2t(float a, float b, uint32_t& hi, uint32_t& lo) {
    uint32_t ua = __float_as_uint(a), ub = __float_as_uint(b);
    hi = __byte_perm(ua, ub, 0x7632);
    float ra = a - __uint_as_float(ua & 0xFFFF0000u);
    float rb = b - __uint_as_float(ub & 0xFFFF0000u);
    asm("cvt.rn.bf16x2.f32 %0, %1, %2;" : "=r"(lo) : "f"(rb), "f"(ra));
}

__device__ __forceinline__ void mma16816(float* c, const uint32_t* a, const uint32_t* b) {
    asm volatile(
        "mma.sync.aligned.m16n8k16.row.col.f32.bf16.bf16.f32 "
        "{%0,%1,%2,%3}, {%4,%5,%6,%7}, {%8,%9}, {%0,%1,%2,%3};"
        : "+f"(c[0]), "+f"(c[1]), "+f"(c[2]), "+f"(c[3])
        : "r"(a[0]), "r"(a[1]), "r"(a[2]), "r"(a[3]), "r"(b[0]), "r"(b[1]));
}

#define AS 40        // A smem row stride (ushorts); 80B rows
#define GB_ROW 1056  // e1 B row stride bytes
#define GB_HALF 512
#define GB_ROW2 2080 // e2 B row stride bytes
#define GB_HALF2 1024

// ================= small kernels =================
__global__ void prep_x_kernel(const float* __restrict__ x, int nTot) {
    int i = (blockIdx.x * 256 + threadIdx.x) * 4;
    if (i < nTot) {
        float4 v = *(const float4*)(x + i);
        uint2 H, L;
        split2t(v.x, v.y, H.x, L.x);
        split2t(v.z, v.w, H.y, L.y);
        *(uint2*)&g_x_hi[i] = H;
        *(uint2*)&g_x_lo[i] = L;
    }
}

__global__ void router_kernel(const float* __restrict__ x, const float* __restrict__ gw) {
    int t = blockIdx.x;
    __shared__ float xs[HIDDEN];
    __shared__ float logits[NE];
    int tid = threadIdx.x;
    for (int i = tid; i < HIDDEN; i += 128) xs[i] = x[(size_t)t * HIDDEN + i];
    __syncthreads();
    int warp = tid >> 5, lane = tid & 31;
    for (int e8 = 0; e8 < 8; e8++) {
        int e = warp * 8 + e8;
        const float* w = gw + (size_t)e * HIDDEN;
        float s = 0.f;
        for (int h = lane; h < HIDDEN; h += 32) s += xs[h] * w[h];
        #pragma unroll
        for (int o = 16; o; o >>= 1) s += __shfl_xor_sync(0xffffffffu, s, o);
        if (lane == 0) logits[e] = s;
    }
    __syncthreads();
    if (tid == 0) {
        float mx = -1e30f;
        for (int e = 0; e < NE; e++) mx = fmaxf(mx, logits[e]);
        float p[NE];
        for (int e = 0; e < NE; e++) p[e] = expf(logits[e] - mx);
        bool used[NE] = {};
        float wsum = 0.f; int idx[TOPK]; float wv[TOPK];
        for (int k = 0; k < TOPK; k++) {
            float best = -1.f; int bi = 0;
            for (int e = 0; e < NE; e++)
                if (!used[e] && p[e] > best) { best = p[e]; bi = e; }
            used[bi] = true; idx[k] = bi; wv[k] = best; wsum += best;
        }
        float inv = 1.f / wsum;
        for (int k = 0; k < TOPK; k++) {
            g_topi[t * TOPK + k] = idx[k];
            g_topw[t * TOPK + k] = wv[k] * inv;
        }
    }
}

__global__ void build_kernel(int T) {
    __shared__ int cnt[NE], cur[NE];
    int tid = threadIdx.x;
    int np = T * TOPK;
    if (tid < NE) cnt[tid] = 0;
    __syncthreads();
    for (int p = tid; p < np; p += blockDim.x) atomicAdd(&cnt[g_topi[p]], 1);
    __syncthreads();
    if (tid == 0) {
        int off = 0;
        for (int e = 0; e < NE; e++) {
            g_off[e] = off; g_cnt[e] = cnt[e]; cur[e] = off; off += cnt[e];
        }
    }
    __syncthreads();
    for (int p = tid; p < np; p += blockDim.x) {
        int e = g_topi[p];
        int j = atomicAdd(&cur[e], 1);
        g_pt[j] = p >> 3;
        g_t2p[p] = j;
    }
}

__global__ void combine_kernel(float* __restrict__ y) {
    int t = blockIdx.x, tid = threadIdx.x;
    __shared__ int   pj[TOPK];
    __shared__ float pw[TOPK];
    if (tid < TOPK) { pj[tid] = g_t2p[t * TOPK + tid]; pw[tid] = g_topw[t * TOPK + tid]; }
    __syncthreads();
    #pragma unroll
    for (int h = 0; h < 2; h++) {
        int c = h * 1024 + tid * 4;
        float4 acc = make_float4(0.f, 0.f, 0.f, 0.f);
        #pragma unroll
        for (int k = 0; k < TOPK; k++) {
            const float4 v = *(const float4*)(g_eout + (size_t)pj[k] * HIDDEN + c);
            float w = pw[k];
            acc.x += w * v.x; acc.y += w * v.y; acc.z += w * v.z; acc.w += w * v.w;
        }
        *(float4*)(y + (size_t)t * HIDDEN + c) = acc;
    }
}

// ================= E1 (M128 x N64(g)+N64(u), 512 threads, warp m-skip) =================
// smem: toks @0 (512B) | A x3 @512 (3 x 20480, hi/lo halves of 10240) |
//       B x2 @61952 (2 x (G8448+U8448))
#define E1_A    512
#define E1_ABUF 20480
#define E1_B    61952
#define E1_BSZ  16896
#define E1_SMEM 95744
#define E1_NIT  (HIDDEN / 32)

extern __shared__ __align__(16) char dsm[];

__device__ __forceinline__ void e1_prefA(int tid, const int* toks, uint32_t sb,
                                         int k0, uint32_t abuf) {
    int m = tid >> 2, c4 = tid & 3;
    int t = toks[m];
    int zf = (t >= 0) ? 16 : 0;
    size_t so = (size_t)(t >= 0 ? t : 0) * HIDDEN + k0 + c4 * 8;
    uint32_t d = sb + E1_A + abuf + m * 80 + c4 * 16;
    cpa16z(d, g_x_hi + so, zf);
    cpa16z(d + 10240, g_x_lo + so, zf);
    CP_COMMIT();
}

__global__ __launch_bounds__(512, 1)
void e1_kernel(const float* __restrict__ gate_proj,
               const float* __restrict__ up_proj) {
    int e = blockIdx.x;
    int n = g_cnt[e];
    int mbase = blockIdx.y * 128;
    if (mbase >= n) return;
    int off = g_off[e];
    int nbase = blockIdx.z * 64;

    uint32_t sb = smem_u32(dsm);
    int tid = threadIdx.x, wid = tid >> 5, lane = tid & 31;
    int* toks = (int*)dsm;
    if (tid < 128) { int m = mbase + tid; toks[tid] = (m < n) ? g_pt[off + m] : -1; }
    __syncthreads();

    const float* gp  = gate_proj + (size_t)e * HIDDEN * INTER + nbase;
    const float* up_ = up_proj   + (size_t)e * HIDDEN * INTER + nbase;

    int wm = wid >> 2, wn = wid & 3;           // 4m x 4n warps
    bool wact = (mbase + wm * 32) < n;         // warp-level m-skip
    int g = lane >> 2, tg = lane & 3;
    int lq = lane >> 3, lr = lane & 7;
    int lmoff = ((lq & 1) * 8 + lr) * (AS * 2) + (lq >> 1) * 16;

    int nn2 = tid & 31, kg = tid >> 5;         // n-pair id (32), kp id (16)

    float accg[2][2][4] = {};
    float accu[2][2][4] = {};
    float2 gv2[2], uv2[2];

    // weight LDG: 1 k-pair per thread (kg = kp)
    auto ldw = [&](int k0) {
        int k = kg * 2;
        const float* pg = gp + (size_t)(k0 + k) * INTER + nn2 * 2;
        const float* pu = up_ + (size_t)(k0 + k) * INTER + nn2 * 2;
        gv2[0] = *(const float2*)pg;
        gv2[1] = *(const float2*)(pg + INTER);
        uv2[0] = *(const float2*)pu;
        uv2[1] = *(const float2*)(pu + INTER);
    };
    // convert regs -> B buffer (layout [r][c][n]{hi,lo}, 16B per n-pair)
    auto conv = [&](uint32_t bp_dst) {
        int kp = kg;
        int r = (kp & 3) | ((kp >> 3) << 2);
        int c = (kp >> 2) & 1;
        char* base = dsm + E1_B + bp_dst + r * GB_ROW + c * GB_HALF + nn2 * 16;
        uint4 o;
        split2t(gv2[0].x, gv2[1].x, o.x, o.y);
        split2t(gv2[0].y, gv2[1].y, o.z, o.w);
        *(uint4*)base = o;
        split2t(uv2[0].x, uv2[1].x, o.x, o.y);
        split2t(uv2[0].y, uv2[1].y, o.z, o.w);
        *(uint4*)(base + 8448) = o;
    };

    // prologue
    ldw(0);
    e1_prefA(tid, toks, sb, 0, 0);
    conv(0);
    ldw(32);
    e1_prefA(tid, toks, sb, 32, E1_ABUF);
    CP_WAIT1();
    __syncthreads();

    uint32_t ap_r = 0, ap_w = 2 * E1_ABUF, bp = 0;
    for (int it = 0; it < E1_NIT; it++) {
        // ---- MMA(it): A[ap_r], B[bp] (skipped entirely by inactive m-warps) ----
        if (wact) {
            uint32_t Ah_base = sb + E1_A + ap_r + (wm * 32) * 80 + lmoff;
            #pragma unroll
            for (int kk = 0; kk < 32; kk += 16) {
                uint32_t ah[2][4], al[2][4];
                #pragma unroll
                for (int mf = 0; mf < 2; mf++) {
                    uint32_t aaddr = Ah_base + mf * (16 * 80) + kk * 2;
                    ldsm4(ah[mf], aaddr);
                    ldsm4(al[mf], aaddr + 10240);
                }
                const char* Grow = dsm + E1_B + bp + (tg + (kk >> 2)) * GB_ROW;
                {
                    uint32_t bh[2][2], bl[2][2];
                    #pragma unroll
                    for (int nf = 0; nf < 2; nf++) {
                        int nb = (wn * 16 + nf * 8 + g) * 8;
                        uint2 v0 = *(const uint2*)(Grow + nb);
                        uint2 v1 = *(const uint2*)(Grow + GB_HALF + nb);
                        bh[nf][0] = v0.x; bl[nf][0] = v0.y;
                        bh[nf][1] = v1.x; bl[nf][1] = v1.y;
                    }
                    #pragma unroll
                    for (int mf = 0; mf < 2; mf++)
                    #pragma unroll
                    for (int nf = 0; nf < 2; nf++) {
                        mma16816(accg[mf][nf], ah[mf], bh[nf]);
                        mma16816(accg[mf][nf], ah[mf], bl[nf]);
                        mma16816(accg[mf][nf], al[mf], bh[nf]);
                    }
                }
                {
                    const char* Urow = Grow + 8448;
                    uint32_t bh[2][2], bl[2][2];
                    #pragma unroll
                    for (int nf = 0; nf < 2; nf++) {
                        int nb = (wn * 16 + nf * 8 + g) * 8;
                        uint2 v0 = *(const uint2*)(Urow + nb);
                        uint2 v1 = *(const uint2*)(Urow + GB_HALF + nb);
                        bh[nf][0] = v0.x; bl[nf][0] = v0.y;
                        bh[nf][1] = v1.x; bl[nf][1] = v1.y;
                    }
                    #pragma unroll
                    for (int mf = 0; mf < 2; mf++)
                    #pragma unroll
                    for (int nf = 0; nf < 2; nf++) {
                        mma16816(accu[mf][nf], ah[mf], bh[nf]);
                        mma16816(accu[mf][nf], ah[mf], bl[nf]);
                        mma16816(accu[mf][nf], al[mf], bh[nf]);
                    }
                }
            }
        }

        // ---- convert(it+1) into other B buffer ----
        if (it + 1 < E1_NIT) conv(bp ^ E1_BSZ);
        // ---- prefetch it+2 ----
        if (it + 2 < E1_NIT) {
            ldw((it + 2) * 32);
            e1_prefA(tid, toks, sb, (it + 2) * 32, ap_w);
            CP_WAIT1();
        } else if (it + 1 < E1_NIT) {
            CP_WAIT0();
        }
        __syncthreads();
        bp ^= E1_BSZ;
        ap_r = (ap_r == 2 * E1_ABUF) ? 0 : ap_r + E1_ABUF;
        ap_w = (ap_w == 2 * E1_ABUF) ? 0 : ap_w + E1_ABUF;
    }

    // ---- epilogue: silu(g)*u -> split bf16 -> g_act (packed 4B stores) ----
    if (wact) {
        #pragma unroll
        for (int mf = 0; mf < 2; mf++)
        #pragma unroll
        for (int nf = 0; nf < 2; nf++)
        #pragma unroll
        for (int half = 0; half < 2; half++) {
            int m = mbase + wm * 32 + mf * 16 + g + half * 8;
            if (m >= n) continue;
            int col = nbase + wn * 16 + nf * 8 + 2 * tg;
            float g0 = accg[mf][nf][half * 2],     u0 = accu[mf][nf][half * 2];
            float g1 = accg[mf][nf][half * 2 + 1], u1 = accu[mf][nf][half * 2 + 1];
            float a0 = (g0 / (1.f + __expf(-g0))) * u0;
            float a1 = (g1 / (1.f + __expf(-g1))) * u1;
            uint32_t hi, lo;
            split2t(a0, a1, hi, lo);
            size_t ai = (size_t)(off + m) * INTER + col;
            *(uint32_t*)&g_act_hi[ai] = hi;
            *(uint32_t*)&g_act_lo[ai] = lo;
        }
    }
}

// ================= E2 (M128 x N128, 512 threads, warp m-skip) =================
// smem: A x3 @0 (3 x 20480) | B x2 @61440 (2 x 16640)
#define E2_A    0
#define E2_ABUF 20480
#define E2_B    61440
#define E2_BSZ  16640
#define E2_SMEM 94720
#define E2_NIT  (INTER / 32)

__device__ __forceinline__ void e2_prefA(int tid, int off, int mbase, int n, uint32_t sb,
                                         int k0, uint32_t abuf) {
    int m = tid >> 2, c4 = tid & 3;
    bool valid = (mbase + m) < n;
    int zf = valid ? 16 : 0;
    size_t so = valid ? ((size_t)(off + mbase + m) * INTER + k0 + c4 * 8) : 0;
    uint32_t d = sb + E2_A + abuf + m * 80 + c4 * 16;
    cpa16z(d, g_act_hi + so, zf);
    cpa16z(d + 10240, g_act_lo + so, zf);
    CP_COMMIT();
}

__global__ __launch_bounds__(512, 1)
void e2_kernel(const float* __restrict__ down_proj) {
    int e = blockIdx.x;
    int n = g_cnt[e];
    int mbase = blockIdx.y * 128;
    if (mbase >= n) return;
    int off = g_off[e];
    int nbase = blockIdx.z * 128;

    uint32_t sb = smem_u32(dsm);
    int tid = threadIdx.x, wid = tid >> 5, lane = tid & 31;
    int wm = wid >> 2, wn = wid & 3;           // 4m x 4n warps
    bool wact = (mbase + wm * 32) < n;         // warp-level m-skip
    int g = lane >> 2, tg = lane & 3;
    int lq = lane >> 3, lr = lane & 7;
    int lmoff = ((lq & 1) * 8 + lr) * (AS * 2) + (lq >> 1) * 16;

    int nn2 = tid & 63, kg = tid >> 6;         // n-pair (64), k-group (8)

    const float* dp = down_proj + (size_t)e * INTER * HIDDEN + nbase;

    float acc[2][4][4] = {};
    float2 bv2[2][2];

    auto ldw = [&](int k0) {
        #pragma unroll
        for (int kpi = 0; kpi < 2; kpi++) {
            int k = (kpi * 8 + kg) * 2;
            const float* pb = dp + (size_t)(k0 + k) * HIDDEN + nn2 * 2;
            bv2[kpi][0] = *(const float2*)pb;
            bv2[kpi][1] = *(const float2*)(pb + HIDDEN);
        }
    };
    auto conv = [&](uint32_t bp_dst) {
        #pragma unroll
        for (int kpi = 0; kpi < 2; kpi++) {
            int kp = kpi * 8 + kg;
            int r = (kp & 3) | ((kp >> 3) << 2);
            int c = (kp >> 2) & 1;
            char* base = dsm + E2_B + bp_dst + r * GB_ROW2 + c * GB_HALF2 + nn2 * 16;
            uint4 o;
            split2t(bv2[kpi][0].x, bv2[kpi][1].x, o.x, o.y);
            split2t(bv2[kpi][0].y, bv2[kpi][1].y, o.z, o.w);
            *(uint4*)base = o;
        }
    };

    ldw(0);
    e2_prefA(tid, off, mbase, n, sb, 0, 0);
    conv(0);
    ldw(32);
    e2_prefA(tid, off, mbase, n, sb, 32, E2_ABUF);
    CP_WAIT1();
    __syncthreads();

    uint32_t ap_r = 0, ap_w = 2 * E2_ABUF, bp = 0;
    for (int it = 0; it < E2_NIT; it++) {
        if (wact) {
            uint32_t Ah_base = sb + E2_A + ap_r + (wm * 32) * 80 + lmoff;
            #pragma unroll
            for (int kk = 0; kk < 32; kk += 16) {
                uint32_t ah[2][4], al[2][4];
                #pragma unroll
                for (int mf = 0; mf < 2; mf++) {
                    uint32_t aaddr = Ah_base + mf * (16 * 80) + kk * 2;
                    ldsm4(ah[mf], aaddr);
                    ldsm4(al[mf], aaddr + 10240);
                }
                const char* Brow = dsm + E2_B + bp + (tg + (kk >> 2)) * GB_ROW2;
                uint32_t bh[4][2], bl[4][2];
                #pragma unroll
                for (int nf = 0; nf < 4; nf++) {
                    int nb = (wn * 32 + nf * 8 + g) * 8;
                    uint2 v0 = *(const uint2*)(Brow + nb);
                    uint2 v1 = *(const uint2*)(Brow + GB_HALF2 + nb);
                    bh[nf][0] = v0.x; bl[nf][0] = v0.y;
                    bh[nf][1] = v1.x; bl[nf][1] = v1.y;
                }
                #pragma unroll
                for (int mf = 0; mf < 2; mf++)
                #pragma unroll
                for (int nf = 0; nf < 4; nf++) {
                    mma16816(acc[mf][nf], ah[mf], bh[nf]);
                    mma16816(acc[mf][nf], ah[mf], bl[nf]);
                    mma16816(acc[mf][nf], al[mf], bh[nf]);
                }
            }
        }

        if (it + 1 < E2_NIT) conv(bp ^ E2_BSZ);
        if (it + 2 < E2_NIT) {
            ldw((it + 2) * 32);
            e2_prefA(tid, off, mbase, n, sb, (it + 2) * 32, ap_w);
            CP_WAIT1();
        } else if (it + 1 < E2_NIT) {
            CP_WAIT0();
        }
        __syncthreads();
        bp ^= E2_BSZ;
        ap_r = (ap_r == 2 * E2_ABUF) ? 0 : ap_r + E2_ABUF;
        ap_w = (ap_w == 2 * E2_ABUF) ? 0 : ap_w + E2_ABUF;
    }

    // ---- epilogue: raw per-pair output rows ----
    if (wact) {
        #pragma unroll
        for (int mf = 0; mf < 2; mf++) {
            #pragma unroll
            for (int half = 0; half < 2; half++) {
                int m = mbase + wm * 32 + mf * 16 + g + half * 8;
                if (m >= n) continue;
                float* orow = g_eout + (size_t)(off + m) * HIDDEN + nbase;
                #pragma unroll
                for (int nf = 0; nf < 4; nf++) {
                    int col = wn * 32 + nf * 8 + 2 * tg;
                    float2 v = make_float2(acc[mf][nf][half * 2], acc[mf][nf][half * 2 + 1]);
                    *(float2*)&orow[col] = v;
                }
            }
        }
    }
}

// ================= launch =================
extern "C" void kernel_launch(void* const* d_in, const int* in_sizes, int n_in,
                              void* d_out, int out_size) {
    const float* x  = (const float*)d_in[0];
    const float* gw = (const float*)d_in[1];
    const float* gp = (const float*)d_in[2];
    const float* up = (const float*)d_in[3];
    const float* dp = (const float*)d_in[4];
    float* y = (float*)d_out;

    int T = in_sizes[0] / HIDDEN;
    int nTot = T * HIDDEN;

    cudaFuncSetAttribute(e1_kernel, cudaFuncAttributeMaxDynamicSharedMemorySize, E1_SMEM);
    cudaFuncSetAttribute(e2_kernel, cudaFuncAttributeMaxDynamicSharedMemorySize, E2_SMEM);

    prep_x_kernel<<<(nTot / 4 + 255) / 256, 256>>>(x, nTot);
    router_kernel<<<T, 128>>>(x, gw);
    build_kernel<<<1, 512>>>(T);

    dim3 g1(NE, (T + 127) / 128, INTER / 64);    // (32, 4, 12)
    e1_kernel<<<g1, 512, E1_SMEM>>>(gp, up);

    dim3 g2(NE, (T + 127) / 128, HIDDEN / 128);  // (32, 4, 16)
    e2_kernel<<<g2, 512, E2_SMEM>>>(dp);

    combine_kernel<<<T, 256>>>(y);
}

// round 14
// speedup vs baseline: 1.2845x; 1.0419x over previous
#include <cuda_runtime.h>
#include <cuda_bf16.h>
#include <math.h>
#include <stdint.h>

#define HIDDEN 2048
#define INTER  768
#define NE     32
#define TOPK   8
#define MAXT   512
#define MAXP   (MAXT * TOPK)

typedef unsigned short ushort_t;

// ---- scratch (device globals) ----
__device__ float g_topw[MAXP];
__device__ int   g_topi[MAXP];
__device__ int   g_cnt[NE];
__device__ int   g_off[NE];
__device__ int   g_pt[MAXP];
__device__ int   g_t2p[MAXP];
__device__ ushort_t g_x_hi[(size_t)MAXT * HIDDEN];
__device__ ushort_t g_x_lo[(size_t)MAXT * HIDDEN];
__device__ ushort_t g_act_hi[(size_t)MAXP * INTER];
__device__ ushort_t g_act_lo[(size_t)MAXP * INTER];
__device__ float g_eout[(size_t)MAXP * HIDDEN];

// ================= helpers =================
__device__ __forceinline__ uint32_t smem_u32(const void* p) {
    uint32_t a;
    asm("{ .reg .u64 t; cvta.to.shared.u64 t, %1; cvt.u32.u64 %0, t; }" : "=r"(a) : "l"(p));
    return a;
}
__device__ __forceinline__ void cpa16z(uint32_t dst, const void* src, int zf) {
    asm volatile("cp.async.ca.shared.global [%0], [%1], 16, %2;" :: "r"(dst), "l"(src), "r"(zf));
}
#define CP_COMMIT() asm volatile("cp.async.commit_group;" ::: "memory")
#define CP_WAIT0()  asm volatile("cp.async.wait_group 0;" ::: "memory")
#define CP_WAIT1()  asm volatile("cp.async.wait_group 1;" ::: "memory")

__device__ __forceinline__ void ldsm4(uint32_t* r, uint32_t addr) {
    asm volatile("ldmatrix.sync.aligned.m8n8.x4.shared.b16 {%0,%1,%2,%3}, [%4];"
        : "=r"(r[0]), "=r"(r[1]), "=r"(r[2]), "=r"(r[3]) : "r"(addr));
}

__device__ __forceinline__ unsigned short bfh(float v) { return __bfloat16_as_ushort(__float2bfloat16(v)); }

// cheap split: hi = truncated top-16 bits (exact residual), lo = RN-bf16 of residual
__device__ __forceinline__ void split2t(float a, float b, uint32_t& hi, uint32_t& lo) {
    uint32_t ua = __float_as_uint(a), ub = __float_as_uint(b);
    hi = __byte_perm(ua, ub, 0x7632);
    float ra = a - __uint_as_float(ua & 0xFFFF0000u);
    float rb = b - __uint_as_float(ub & 0xFFFF0000u);
    asm("cvt.rn.bf16x2.f32 %0, %1, %2;" : "=r"(lo) : "f"(rb), "f"(ra));
}

__device__ __forceinline__ void mma16816(float* c, const uint32_t* a, const uint32_t* b) {
    asm volatile(
        "mma.sync.aligned.m16n8k16.row.col.f32.bf16.bf16.f32 "
        "{%0,%1,%2,%3}, {%4,%5,%6,%7}, {%8,%9}, {%0,%1,%2,%3};"
        : "+f"(c[0]), "+f"(c[1]), "+f"(c[2]), "+f"(c[3])
        : "r"(a[0]), "r"(a[1]), "r"(a[2]), "r"(a[3]), "r"(b[0]), "r"(b[1]));
}

#define AS 40        // A smem row stride (ushorts); 80B rows
#define GB_ROW 1056  // e1 B row stride bytes
#define GB_HALF 512
#define E2_BROW 4128 // e2 B row stride bytes (N256: 128 n-pairs x 16B x 2c + 32 pad)
#define E2_BHALF 2048

// ================= small kernels =================
__global__ void prep_x_kernel(const float* __restrict__ x, int nTot) {
    int i = (blockIdx.x * 256 + threadIdx.x) * 4;
    if (i < nTot) {
        float4 v = *(const float4*)(x + i);
        uint2 H, L;
        split2t(v.x, v.y, H.x, L.x);
        split2t(v.z, v.w, H.y, L.y);
        *(uint2*)&g_x_hi[i] = H;
        *(uint2*)&g_x_lo[i] = L;
    }
}

__global__ void router_kernel(const float* __restrict__ x, const float* __restrict__ gw) {
    int t = blockIdx.x;
    __shared__ float xs[HIDDEN];
    __shared__ float logits[NE];
    int tid = threadIdx.x;
    for (int i = tid; i < HIDDEN; i += 128) xs[i] = x[(size_t)t * HIDDEN + i];
    __syncthreads();
    int warp = tid >> 5, lane = tid & 31;
    for (int e8 = 0; e8 < 8; e8++) {
        int e = warp * 8 + e8;
        const float* w = gw + (size_t)e * HIDDEN;
        float s = 0.f;
        for (int h = lane; h < HIDDEN; h += 32) s += xs[h] * w[h];
        #pragma unroll
        for (int o = 16; o; o >>= 1) s += __shfl_xor_sync(0xffffffffu, s, o);
        if (lane == 0) logits[e] = s;
    }
    __syncthreads();
    if (tid == 0) {
        float mx = -1e30f;
        for (int e = 0; e < NE; e++) mx = fmaxf(mx, logits[e]);
        float p[NE];
        for (int e = 0; e < NE; e++) p[e] = expf(logits[e] - mx);
        bool used[NE] = {};
        float wsum = 0.f; int idx[TOPK]; float wv[TOPK];
        for (int k = 0; k < TOPK; k++) {
            float best = -1.f; int bi = 0;
            for (int e = 0; e < NE; e++)
                if (!used[e] && p[e] > best) { best = p[e]; bi = e; }
            used[bi] = true; idx[k] = bi; wv[k] = best; wsum += best;
        }
        float inv = 1.f / wsum;
        for (int k = 0; k < TOPK; k++) {
            g_topi[t * TOPK + k] = idx[k];
            g_topw[t * TOPK + k] = wv[k] * inv;
        }
    }
}

__global__ void build_kernel(int T) {
    __shared__ int cnt[NE], cur[NE];
    int tid = threadIdx.x;
    int np = T * TOPK;
    if (tid < NE) cnt[tid] = 0;
    __syncthreads();
    for (int p = tid; p < np; p += blockDim.x) atomicAdd(&cnt[g_topi[p]], 1);
    __syncthreads();
    if (tid == 0) {
        int off = 0;
        for (int e = 0; e < NE; e++) {
            g_off[e] = off; g_cnt[e] = cnt[e]; cur[e] = off; off += cnt[e];
        }
    }
    __syncthreads();
    for (int p = tid; p < np; p += blockDim.x) {
        int e = g_topi[p];
        int j = atomicAdd(&cur[e], 1);
        g_pt[j] = p >> 3;
        g_t2p[p] = j;
    }
}

__global__ void combine_kernel(float* __restrict__ y) {
    int t = blockIdx.x, tid = threadIdx.x;
    __shared__ int   pj[TOPK];
    __shared__ float pw[TOPK];
    if (tid < TOPK) { pj[tid] = g_t2p[t * TOPK + tid]; pw[tid] = g_topw[t * TOPK + tid]; }
    __syncthreads();
    #pragma unroll
    for (int h = 0; h < 2; h++) {
        int c = h * 1024 + tid * 4;
        float4 acc = make_float4(0.f, 0.f, 0.f, 0.f);
        #pragma unroll
        for (int k = 0; k < TOPK; k++) {
            const float4 v = *(const float4*)(g_eout + (size_t)pj[k] * HIDDEN + c);
            float w = pw[k];
            acc.x += w * v.x; acc.y += w * v.y; acc.z += w * v.z; acc.w += w * v.w;
        }
        *(float4*)(y + (size_t)t * HIDDEN + c) = acc;
    }
}

// ================= E1 (R9 config: M64 x N64(g)+N64(u), 256 threads, 2 CTA/SM) =====
// smem: toks @0 (256B) | A x3 @256 (3 x 10240) | B x2 @30976 (2 x (G8448+U8448))
#define E1_A    256
#define E1_B    30976
#define E1_BSZ  16896
#define E1_SMEM 64768
#define E1_NIT  (HIDDEN / 32)

extern __shared__ __align__(16) char dsm[];

__device__ __forceinline__ void e1_prefA(int tid, const int* toks, uint32_t sb,
                                         int k0, uint32_t abuf) {
    int m = tid >> 2, c4 = tid & 3;
    int t = toks[m];
    int zf = (t >= 0) ? 16 : 0;
    size_t so = (size_t)(t >= 0 ? t : 0) * HIDDEN + k0 + c4 * 8;
    uint32_t d = sb + E1_A + abuf + m * 80 + c4 * 16;
    cpa16z(d, g_x_hi + so, zf);
    cpa16z(d + 5120, g_x_lo + so, zf);
    CP_COMMIT();
}

__global__ __launch_bounds__(256, 2)
void e1_kernel(const float* __restrict__ gate_proj,
               const float* __restrict__ up_proj) {
    int e = blockIdx.x;
    int n = g_cnt[e];
    int mbase = blockIdx.y * 64;
    if (mbase >= n) return;
    int off = g_off[e];
    int nbase = blockIdx.z * 64;

    uint32_t sb = smem_u32(dsm);
    int tid = threadIdx.x, wid = tid >> 5, lane = tid & 31;
    int* toks = (int*)dsm;
    if (tid < 64) { int m = mbase + tid; toks[tid] = (m < n) ? g_pt[off + m] : -1; }
    __syncthreads();

    const float* gp  = gate_proj + (size_t)e * HIDDEN * INTER + nbase;
    const float* up_ = up_proj   + (size_t)e * HIDDEN * INTER + nbase;

    int wm = wid >> 2, wn = wid & 3;
    int g = lane >> 2, tg = lane & 3;
    int lq = lane >> 3, lr = lane & 7;
    int lmoff = ((lq & 1) * 8 + lr) * (AS * 2) + (lq >> 1) * 16;

    int nn2 = tid & 31, kg = tid >> 5;     // n-pair id, k-group

    float accg[2][2][4] = {};
    float accu[2][2][4] = {};
    float2 gv2[2], uv2[2];

    // weight LDG (consumed one iter later by convert)
    auto ldw = [&](int k0) {
        #pragma unroll
        for (int kpi = 0; kpi < 2; kpi++) {
            int k = (kpi * 8 + kg) * 2;
            const float* pg = gp + (size_t)(k0 + k) * INTER + nn2 * 2;
            const float* pu = up_ + (size_t)(k0 + k) * INTER + nn2 * 2;
            if (kpi == 0) { gv2[0] = *(const float2*)pg; gv2[1] = *(const float2*)(pg + INTER);
                            uv2[0] = *(const float2*)pu; uv2[1] = *(const float2*)(pu + INTER); }
        }
    };
    // NOTE: the R9 version used gv2[2][2]; restore exactly:
    (void)ldw;
    float2 gva[2][2], uva[2][2];
    auto ldw2 = [&](int k0) {
        #pragma unroll
        for (int kpi = 0; kpi < 2; kpi++) {
            int k = (kpi * 8 + kg) * 2;
            const float* pg = gp + (size_t)(k0 + k) * INTER + nn2 * 2;
            const float* pu = up_ + (size_t)(k0 + k) * INTER + nn2 * 2;
            gva[kpi][0] = *(const float2*)pg;
            gva[kpi][1] = *(const float2*)(pg + INTER);
            uva[kpi][0] = *(const float2*)pu;
            uva[kpi][1] = *(const float2*)(pu + INTER);
        }
    };
    auto conv = [&](uint32_t bp_dst) {
        #pragma unroll
        for (int kpi = 0; kpi < 2; kpi++) {
            int kp = kpi * 8 + kg;
            int r = (kp & 3) | ((kp >> 3) << 2);
            int c = (kp >> 2) & 1;
            char* base = dsm + E1_B + bp_dst + r * GB_ROW + c * GB_HALF + nn2 * 16;
            uint4 o;
            split2t(gva[kpi][0].x, gva[kpi][1].x, o.x, o.y);
            split2t(gva[kpi][0].y, gva[kpi][1].y, o.z, o.w);
            *(uint4*)base = o;
            split2t(uva[kpi][0].x, uva[kpi][1].x, o.x, o.y);
            split2t(uva[kpi][0].y, uva[kpi][1].y, o.z, o.w);
            *(uint4*)(base + 8448) = o;
        }
    };

    // prologue
    ldw2(0);
    e1_prefA(tid, toks, sb, 0, 0);
    conv(0);
    ldw2(32);
    e1_prefA(tid, toks, sb, 32, 10240);
    CP_WAIT1();
    __syncthreads();

    uint32_t ap_r = 0, ap_w = 20480, bp = 0;
    for (int it = 0; it < E1_NIT; it++) {
        // ---- MMA(it): A[ap_r], B[bp] ----
        uint32_t Ah_base = sb + E1_A + ap_r + (wm * 32) * 80 + lmoff;
        #pragma unroll
        for (int kk = 0; kk < 32; kk += 16) {
            uint32_t ah[2][4], al[2][4];
            #pragma unroll
            for (int mf = 0; mf < 2; mf++) {
                uint32_t aaddr = Ah_base + mf * (16 * 80) + kk * 2;
                ldsm4(ah[mf], aaddr);
                ldsm4(al[mf], aaddr + 5120);
            }
            const char* Grow = dsm + E1_B + bp + (tg + (kk >> 2)) * GB_ROW;
            {
                uint32_t bh[2][2], bl[2][2];
                #pragma unroll
                for (int nf = 0; nf < 2; nf++) {
                    int nb = (wn * 16 + nf * 8 + g) * 8;
                    uint2 v0 = *(const uint2*)(Grow + nb);
                    uint2 v1 = *(const uint2*)(Grow + GB_HALF + nb);
                    bh[nf][0] = v0.x; bl[nf][0] = v0.y;
                    bh[nf][1] = v1.x; bl[nf][1] = v1.y;
                }
                #pragma unroll
                for (int mf = 0; mf < 2; mf++)
                #pragma unroll
                for (int nf = 0; nf < 2; nf++) {
                    mma16816(accg[mf][nf], ah[mf], bh[nf]);
                    mma16816(accg[mf][nf], ah[mf], bl[nf]);
                    mma16816(accg[mf][nf], al[mf], bh[nf]);
                }
            }
            {
                const char* Urow = Grow + 8448;
                uint32_t bh[2][2], bl[2][2];
                #pragma unroll
                for (int nf = 0; nf < 2; nf++) {
                    int nb = (wn * 16 + nf * 8 + g) * 8;
                    uint2 v0 = *(const uint2*)(Urow + nb);
                    uint2 v1 = *(const uint2*)(Urow + GB_HALF + nb);
                    bh[nf][0] = v0.x; bl[nf][0] = v0.y;
                    bh[nf][1] = v1.x; bl[nf][1] = v1.y;
                }
                #pragma unroll
                for (int mf = 0; mf < 2; mf++)
                #pragma unroll
                for (int nf = 0; nf < 2; nf++) {
                    mma16816(accu[mf][nf], ah[mf], bh[nf]);
                    mma16816(accu[mf][nf], ah[mf], bl[nf]);
                    mma16816(accu[mf][nf], al[mf], bh[nf]);
                }
            }
        }

        // ---- convert(it+1) into other B buffer (overlaps tensor drain) ----
        if (it + 1 < E1_NIT) conv(bp ^ E1_BSZ);
        // ---- prefetch it+2 ----
        if (it + 2 < E1_NIT) {
            ldw2((it + 2) * 32);
            e1_prefA(tid, toks, sb, (it + 2) * 32, ap_w);
            CP_WAIT1();
        } else if (it + 1 < E1_NIT) {
            CP_WAIT0();
        }
        __syncthreads();
        bp ^= E1_BSZ;
        ap_r = (ap_r == 20480) ? 0 : ap_r + 10240;
        ap_w = (ap_w == 20480) ? 0 : ap_w + 10240;
    }

    // ---- epilogue: silu(g)*u -> split bf16 -> g_act (packed 4B stores) ----
    #pragma unroll
    for (int mf = 0; mf < 2; mf++)
    #pragma unroll
    for (int nf = 0; nf < 2; nf++)
    #pragma unroll
    for (int half = 0; half < 2; half++) {
        int m = mbase + wm * 32 + mf * 16 + g + half * 8;
        if (m >= n) continue;
        int col = nbase + wn * 16 + nf * 8 + 2 * tg;
        float g0 = accg[mf][nf][half * 2],     u0 = accu[mf][nf][half * 2];
        float g1 = accg[mf][nf][half * 2 + 1], u1 = accu[mf][nf][half * 2 + 1];
        float a0 = (g0 / (1.f + __expf(-g0))) * u0;
        float a1 = (g1 / (1.f + __expf(-g1))) * u1;
        uint32_t hi, lo;
        split2t(a0, a1, hi, lo);
        size_t ai = (size_t)(off + m) * INTER + col;
        *(uint32_t*)&g_act_hi[ai] = hi;
        *(uint32_t*)&g_act_lo[ai] = lo;
    }
}

// ================= E2 (M64 x N256, 512 threads, 1 CTA/SM) =================
// smem: A x3 @0 (3 x 10240) | B x2 @30720 (2 x 66048)
#define E2_A    0
#define E2_ABUF 10240
#define E2_B    30720
#define E2_BSZ  66048
#define E2_SMEM 162816
#define E2_NIT  (INTER / 32)

__device__ __forceinline__ void e2_prefA(int tid, int off, int mbase, int n, uint32_t sb,
                                         int k0, uint32_t abuf) {
    int half = tid >> 8;                   // 0: hi, 1: lo
    int idx = tid & 255;
    int m = idx >> 2, c4 = idx & 3;
    bool valid = (mbase + m) < n;
    int zf = valid ? 16 : 0;
    size_t so = valid ? ((size_t)(off + mbase + m) * INTER + k0 + c4 * 8) : 0;
    const ushort_t* srcp = half ? g_act_lo : g_act_hi;
    uint32_t d = sb + E2_A + abuf + half * 5120 + m * 80 + c4 * 16;
    cpa16z(d, srcp + so, zf);
    CP_COMMIT();
}

__global__ __launch_bounds__(512, 1)
void e2_kernel(const float* __restrict__ down_proj) {
    int e = blockIdx.x;
    int n = g_cnt[e];
    int mbase = blockIdx.y * 64;
    if (mbase >= n) return;
    int off = g_off[e];
    int nbase = blockIdx.z * 256;

    uint32_t sb = smem_u32(dsm);
    int tid = threadIdx.x, wid = tid >> 5, lane = tid & 31;
    int wm = wid >> 3, wn = wid & 7;           // 2m x 8n warps
    bool wact = (mbase + wm * 32) < n;
    int g = lane >> 2, tg = lane & 3;
    int lq = lane >> 3, lr = lane & 7;
    int lmoff = ((lq & 1) * 8 + lr) * (AS * 2) + (lq >> 1) * 16;

    int nn2 = tid & 127, kg = tid >> 7;        // n-pair (128), k-group (4)

    const float* dp = down_proj + (size_t)e * INTER * HIDDEN + nbase;

    float acc[2][4][4] = {};
    float2 bv2[4][2];

    auto ldw = [&](int k0) {
        #pragma unroll
        for (int kpi = 0; kpi < 4; kpi++) {
            int k = (kpi * 4 + kg) * 2;
            const float* pb = dp + (size_t)(k0 + k) * HIDDEN + nn2 * 2;
            bv2[kpi][0] = *(const float2*)pb;
            bv2[kpi][1] = *(const float2*)(pb + HIDDEN);
        }
    };
    auto conv = [&](uint32_t bp_dst) {
        #pragma unroll
        for (int kpi = 0; kpi < 4; kpi++) {
            int kp = kpi * 4 + kg;
            int r = (kp & 3) | ((kp >> 3) << 2);
            int c = (kp >> 2) & 1;
            char* base = dsm + E2_B + bp_dst + r * E2_BROW + c * E2_BHALF + nn2 * 16;
            uint4 o;
            split2t(bv2[kpi][0].x, bv2[kpi][1].x, o.x, o.y);
            split2t(bv2[kpi][0].y, bv2[kpi][1].y, o.z, o.w);
            *(uint4*)base = o;
        }
    };

    ldw(0);
    e2_prefA(tid, off, mbase, n, sb, 0, 0);
    conv(0);
    ldw(32);
    e2_prefA(tid, off, mbase, n, sb, 32, E2_ABUF);
    CP_WAIT1();
    __syncthreads();

    uint32_t ap_r = 0, ap_w = 2 * E2_ABUF, bp = 0;
    for (int it = 0; it < E2_NIT; it++) {
        if (wact) {
            uint32_t Ah_base = sb + E2_A + ap_r + (wm * 32) * 80 + lmoff;
            #pragma unroll
            for (int kk = 0; kk < 32; kk += 16) {
                uint32_t ah[2][4], al[2][4];
                #pragma unroll
                for (int mf = 0; mf < 2; mf++) {
                    uint32_t aaddr = Ah_base + mf * (16 * 80) + kk * 2;
                    ldsm4(ah[mf], aaddr);
                    ldsm4(al[mf], aaddr + 5120);
                }
                const char* Brow = dsm + E2_B + bp + (tg + (kk >> 2)) * E2_BROW;
                uint32_t bh[4][2], bl[4][2];
                #pragma unroll
                for (int nf = 0; nf < 4; nf++) {
                    int nb = (wn * 32 + nf * 8 + g) * 8;
                    uint2 v0 = *(const uint2*)(Brow + nb);
                    uint2 v1 = *(const uint2*)(Brow + E2_BHALF + nb);
                    bh[nf][0] = v0.x; bl[nf][0] = v0.y;
                    bh[nf][1] = v1.x; bl[nf][1] = v1.y;
                }
                #pragma unroll
                for (int mf = 0; mf < 2; mf++)
                #pragma unroll
                for (int nf = 0; nf < 4; nf++) {
                    mma16816(acc[mf][nf], ah[mf], bh[nf]);
                    mma16816(acc[mf][nf], ah[mf], bl[nf]);
                    mma16816(acc[mf][nf], al[mf], bh[nf]);
                }
            }
        }

        if (it + 1 < E2_NIT) conv(bp ^ E2_BSZ);
        if (it + 2 < E2_NIT) {
            ldw((it + 2) * 32);
            e2_prefA(tid, off, mbase, n, sb, (it + 2) * 32, ap_w);
            CP_WAIT1();
        } else if (it + 1 < E2_NIT) {
            CP_WAIT0();
        }
        __syncthreads();
        bp ^= E2_BSZ;
        ap_r = (ap_r == 2 * E2_ABUF) ? 0 : ap_r + E2_ABUF;
        ap_w = (ap_w == 2 * E2_ABUF) ? 0 : ap_w + E2_ABUF;
    }

    // ---- epilogue: raw per-pair output rows ----
    if (wact) {
        #pragma unroll
        for (int mf = 0; mf < 2; mf++) {
            #pragma unroll
            for (int half = 0; half < 2; half++) {
                int m = mbase + wm * 32 + mf * 16 + g + half * 8;
                if (m >= n) continue;
                float* orow = g_eout + (size_t)(off + m) * HIDDEN + nbase;
                #pragma unroll
                for (int nf = 0; nf < 4; nf++) {
                    int col = wn * 32 + nf * 8 + 2 * tg;
                    float2 v = make_float2(acc[mf][nf][half * 2], acc[mf][nf][half * 2 + 1]);
                    *(float2*)&orow[col] = v;
                }
            }
        }
    }
}

// ================= launch =================
extern "C" void kernel_launch(void* const* d_in, const int* in_sizes, int n_in,
                              void* d_out, int out_size) {
    const float* x  = (const float*)d_in[0];
    const float* gw = (const float*)d_in[1];
    const float* gp = (const float*)d_in[2];
    const float* up = (const float*)d_in[3];
    const float* dp = (const float*)d_in[4];
    float* y = (float*)d_out;

    int T = in_sizes[0] / HIDDEN;
    int nTot = T * HIDDEN;

    cudaFuncSetAttribute(e1_kernel, cudaFuncAttributeMaxDynamicSharedMemorySize, E1_SMEM);
    cudaFuncSetAttribute(e2_kernel, cudaFuncAttributeMaxDynamicSharedMemorySize, E2_SMEM);

    prep_x_kernel<<<(nTot / 4 + 255) / 256, 256>>>(x, nTot);
    router_kernel<<<T, 128>>>(x, gw);
    build_kernel<<<1, 512>>>(T);

    dim3 g1(NE, (T + 63) / 64, INTER / 64);    // (32, 8, 12)
    e1_kernel<<<g1, 256, E1_SMEM>>>(gp, up);

    dim3 g2(NE, (T + 63) / 64, HIDDEN / 256);  // (32, 8, 8)
    e2_kernel<<<g2, 512, E2_SMEM>>>(dp);

    combine_kernel<<<T, 256>>>(y);
}